// round 16
// baseline (speedup 1.0000x reference)
#include <cuda_runtime.h>
#include <cuda_fp16.h>
#include <cstdint>

#define BB 8
#define CC 128
#define TT 128
#define FF 512
#define KK 64
#define S_SIDE (TT*FF)
#define S_LAT  (TT*KK)

typedef unsigned long long u64;
typedef unsigned int u32;
typedef unsigned short u16;

// ---------------- scratch ----------------
__device__ float g_buf2[BB*CC*S_SIDE];            // q (fp32)
__device__ float g_buf3[BB*CC*S_SIDE];            // query_h (fp32, for skip)
__device__ float g_k  [BB*CC*S_LAT];
__device__ float g_v  [BB*CC*S_LAT];
__device__ float g_qbias[CC];                     // folded q bias

// fp16 tile buffers: per (b,tile128): 16384 u16
__device__ u16 g_tA[8*512*16384];                 // glu1 out / glu2 out
__device__ u16 g_tL[8*64*16384];                  // latent_h

// pre-converted fp16 weights
#define WLP 0
#define WK  16384
#define WV  32768
#define WQO 49152
#define WO  65536
#define WFO 81920
#define WQI 98304
#define WFI 131072
#define WQF 163840
__device__ u16 g_wbf[180224];

__device__ __forceinline__ float silu_f(float x) { return x / (1.0f + __expf(-x)); }
__device__ __forceinline__ u64 dup2(float v) {
    u64 r; asm("mov.b64 %0, {%1, %2};" : "=l"(r) : "f"(v), "f"(v)); return r;
}
__device__ __forceinline__ void fma2(u64& d, u64 a, u64 b) {
    asm("fma.rn.f32x2 %0, %1, %2, %0;" : "+l"(d) : "l"(a), "l"(b));
}
__device__ __forceinline__ float2 unpack2(u64 v) {
    float2 r; asm("mov.b64 {%0, %1}, %2;" : "=f"(r.x), "=f"(r.y) : "l"(v)); return r;
}
__device__ __forceinline__ u32 smem_u32(const void* p) {
    u32 a;
    asm("{ .reg .u64 t; cvta.to.shared.u64 t, %1; cvt.u32.u64 %0, t; }" : "=r"(a) : "l"(p));
    return a;
}

// ---------------- mma.sync helpers (fp16) ----------------
__device__ __forceinline__ void ldsm4(u32* r, u32 addr) {
    asm volatile("ldmatrix.sync.aligned.m8n8.x4.shared.b16 {%0,%1,%2,%3}, [%4];"
                 : "=r"(r[0]), "=r"(r[1]), "=r"(r[2]), "=r"(r[3]) : "r"(addr));
}
__device__ __forceinline__ void mma16816(float* d, const u32* a, const u32* b) {
    asm volatile("mma.sync.aligned.m16n8k16.row.col.f32.f16.f16.f32 "
                 "{%0,%1,%2,%3}, {%4,%5,%6,%7}, {%8,%9}, {%0,%1,%2,%3};"
                 : "+f"(d[0]), "+f"(d[1]), "+f"(d[2]), "+f"(d[3])
                 : "r"(a[0]), "r"(a[1]), "r"(a[2]), "r"(a[3]), "r"(b[0]), "r"(b[1]));
}
__device__ __forceinline__ void cpa16(u32 saddr, const void* g) {
    asm volatile("cp.async.cg.shared.global [%0], [%1], 16;" :: "r"(saddr), "l"(g));
}
#define CP_COMMIT() asm volatile("cp.async.commit_group;" ::: "memory")
#define CP_WAIT0()  asm volatile("cp.async.wait_group 0;" ::: "memory")

#define TSTR  272
#define TILE_B (128*TSTR)
#define TPH 136

__device__ __forceinline__ void cvt_store4h(char* smem, u32 base, int row, int col, float4 x) {
    __half h0 = __float2half_rn(x.x);
    __half h1 = __float2half_rn(x.y);
    __half h2 = __float2half_rn(x.z);
    __half h3 = __float2half_rn(x.w);
    u64 hv = (u64)*(u16*)&h0 | ((u64)*(u16*)&h1 << 16) | ((u64)*(u16*)&h2 << 32) | ((u64)*(u16*)&h3 << 48);
    *(u64*)(smem + base + (u32)(row * TSTR + col * 2)) = hv;
}

__device__ __forceinline__ void stage_tile(u32 sbase, const u16* g, int tid) {
    #pragma unroll
    for (int it = 0; it < 8; it++) {
        int idx = tid + it * 256;
        int r = idx >> 4, ch = idx & 15;
        cpa16(sbase + r * TSTR + ch * 16, g + r * 128 + ch * 8);
    }
}

// single-A k-loop; warp covers 32m x 64n
__device__ __forceinline__ void mm_pass(u32 ab, u32 bb, float (*acc)[8][4],
                                        u32 a_row, u32 a_koff, u32 b_row, u32 b_koff,
                                        int n_blk)
{
    #pragma unroll
    for (int ks = 0; ks < 8; ks++) {
        int k0 = ks * 16;
        u32 af[2][4], bf[4][4];
        #pragma unroll
        for (int i = 0; i < 2; i++)
            ldsm4(af[i], ab + (a_row + i * 16) * TSTR + (k0 + a_koff) * 2);
        #pragma unroll
        for (int j = 0; j < 4; j++)
            ldsm4(bf[j], bb + (n_blk + j * 16 + b_row) * TSTR + (k0 + b_koff) * 2);
        #pragma unroll
        for (int i = 0; i < 2; i++)
            #pragma unroll
            for (int j = 0; j < 8; j++)
                mma16816(acc[i][j], af[i], &bf[j >> 1][(j & 1) * 2]);
    }
}

// dual-A k-loop: bf loaded once for both A tiles
__device__ __forceinline__ void mm_pass2(u32 a0, u32 a1, u32 bb,
                                         float (*acc0)[8][4], float (*acc1)[8][4],
                                         u32 a_row, u32 a_koff, u32 b_row, u32 b_koff,
                                         int n_blk)
{
    #pragma unroll
    for (int ks = 0; ks < 8; ks++) {
        int k0 = ks * 16;
        u32 af0[2][4], af1[2][4], bf[4][4];
        #pragma unroll
        for (int i = 0; i < 2; i++) {
            ldsm4(af0[i], a0 + (a_row + i * 16) * TSTR + (k0 + a_koff) * 2);
            ldsm4(af1[i], a1 + (a_row + i * 16) * TSTR + (k0 + a_koff) * 2);
        }
        #pragma unroll
        for (int j = 0; j < 4; j++)
            ldsm4(bf[j], bb + (n_blk + j * 16 + b_row) * TSTR + (k0 + b_koff) * 2);
        #pragma unroll
        for (int i = 0; i < 2; i++)
            #pragma unroll
            for (int j = 0; j < 8; j++) {
                mma16816(acc0[i][j], af0[i], &bf[j >> 1][(j & 1) * 2]);
                mma16816(acc1[i][j], af1[i], &bf[j >> 1][(j & 1) * 2]);
            }
    }
}

// ---------------- fused weight pre-convert + q-fold ----------------
__global__ __launch_bounds__(256)
void convert_all(const float* __restrict__ lp_w, const float* __restrict__ k_w,
                 const float* __restrict__ v_w,  const float* __restrict__ qo_w,
                 const float* __restrict__ o_w,  const float* __restrict__ fo_w,
                 const float* __restrict__ qi_w, const float* __restrict__ fi_w,
                 const float* __restrict__ lp_g, const float* __restrict__ qn_g,
                 const float* __restrict__ ffn_g,
                 const float* __restrict__ qw, const float* __restrict__ qob,
                 const float* __restrict__ qb,
                 u16* __restrict__ dst, float* __restrict__ qbias)
{
    int bid = blockIdx.x;
    if (bid >= 640) {   // q-fold blocks: 640..703
        int idx = (bid - 640) * 256 + threadIdx.x;
        int o = idx >> 7, c = idx & 127;
        float s = 0.f;
        #pragma unroll 4
        for (int m = 0; m < 128; m++)
            s += qw[o * 128 + m] * qo_w[m * 128 + c];
        __half h = __float2half_rn(s);
        dst[WQF + idx] = *(u16*)&h;
        if (c == 0) {
            float t = qb[o];
            #pragma unroll 4
            for (int m = 0; m < 128; m++)
                t += qw[o * 128 + m] * qob[m];
            qbias[o] = t;
        }
        return;
    }
    const float* src; const float* gamma = nullptr; int off, n, lb;
    if (bid < 384) {
        int seg = bid >> 6; lb = bid & 63; n = 16384;
        switch (seg) {
            case 0: src = lp_w; gamma = lp_g; off = WLP; break;
            case 1: src = k_w;  off = WK;  break;
            case 2: src = v_w;  off = WV;  break;
            case 3: src = qo_w; off = WQO; break;
            case 4: src = o_w;  off = WO;  break;
            default: src = fo_w; off = WFO; break;
        }
    } else if (bid < 512) {
        lb = bid - 384; src = qi_w; gamma = qn_g; off = WQI; n = 32768;
    } else {
        lb = bid - 512; src = fi_w; gamma = ffn_g; off = WFI; n = 32768;
    }
    int idx = lb * 256 + threadIdx.x;
    if (idx >= n) return;
    float v = src[idx];
    if (gamma) v *= gamma[idx & 127];
    __half h = __float2half_rn(v);
    dst[off + idx] = *(u16*)&h;
}

// ================= fp16 GEMM, fp32 input, fused inv-rms =================
#define T16_A 0
#define T16_B TILE_B
#define T16_SMEM (2*TILE_B + 512)

template<int NORM, int ACT, int OUTFMT>
__global__ __launch_bounds__(256, 2)
void gemm_f16in(const float* __restrict__ X, const u16* __restrict__ wsc,
                const float* __restrict__ bias, float* __restrict__ Y,
                u16* __restrict__ tout, int S)
{
    extern __shared__ char sm[];
    u32 sb = smem_u32(sm);
    float* ssq = (float*)(sm + 2 * TILE_B);
    int tid = threadIdx.x;
    int wid = tid >> 5, lane = tid & 31;
    int b  = blockIdx.y;
    int s0 = blockIdx.x * 128;
    size_t tb = ((size_t)(b * gridDim.x + blockIdx.x)) * 16384;
    const float* Xb = X + (size_t)b * CC * S;

    if (NORM && tid < 128) ssq[tid] = 0.f;
    stage_tile(sb + T16_A, wsc, tid);
    CP_COMMIT();

    float rv[4] = {1.f, 1.f, 1.f, 1.f};
    if (NORM) {
        __syncthreads();
        float local[4] = {0.f, 0.f, 0.f, 0.f};
        #pragma unroll
        for (int i = 0; i < 16; i++) {
            int s = lane + (i & 3) * 32;
            int c0 = ((wid << 2) + (i >> 2)) * 4;
            float4 x4;
            x4.x = Xb[(size_t)(c0 + 0) * S + s0 + s];
            x4.y = Xb[(size_t)(c0 + 1) * S + s0 + s];
            x4.z = Xb[(size_t)(c0 + 2) * S + s0 + s];
            x4.w = Xb[(size_t)(c0 + 3) * S + s0 + s];
            local[i & 3] += x4.x * x4.x + x4.y * x4.y + x4.z * x4.z + x4.w * x4.w;
        }
        #pragma unroll
        for (int j = 0; j < 4; j++)
            atomicAdd(&ssq[lane + j * 32], local[j]);
        __syncthreads();
        #pragma unroll
        for (int j = 0; j < 4; j++)
            rv[j] = rsqrtf(ssq[lane + j * 32] * (1.0f / CC) + 1e-6f);
    }
    #pragma unroll
    for (int i = 0; i < 16; i++) {
        int s = lane + (i & 3) * 32;
        int c0 = ((wid << 2) + (i >> 2)) * 4;
        float4 x4;
        x4.x = Xb[(size_t)(c0 + 0) * S + s0 + s];
        x4.y = Xb[(size_t)(c0 + 1) * S + s0 + s];
        x4.z = Xb[(size_t)(c0 + 2) * S + s0 + s];
        x4.w = Xb[(size_t)(c0 + 3) * S + s0 + s];
        if (NORM) {
            float r = rv[i & 3];
            x4.x *= r; x4.y *= r; x4.z *= r; x4.w *= r;
        }
        cvt_store4h(sm, T16_B, s, c0, x4);
    }

    int m_blk = (wid & 3) * 32;
    int n_blk = (wid >> 2) * 64;
    float acc[2][8][4];
    #pragma unroll
    for (int i = 0; i < 2; i++)
        #pragma unroll
        for (int j = 0; j < 8; j++)
            #pragma unroll
            for (int q = 0; q < 4; q++) acc[i][j][q] = 0.f;

    u32 a_row = (u32)(m_blk + (lane & 15));
    u32 a_koff = (u32)((lane >> 4) << 3);
    u32 b_row = (u32)((lane & 7) + ((lane >> 4) << 3));
    u32 b_koff = (u32)(((lane >> 3) & 1) << 3);

    CP_WAIT0(); __syncthreads();
    mm_pass(sb + T16_A, sb + T16_B, acc, a_row, a_koff, b_row, b_koff, n_blk);

    u16* trans = (u16*)(sm + T16_B);
    if (OUTFMT == 1) __syncthreads();
    #pragma unroll
    for (int i = 0; i < 2; i++) {
        #pragma unroll
        for (int j = 0; j < 8; j++) {
            int c = n_blk + j * 8 + (lane & 3) * 2;
            #pragma unroll
            for (int h = 0; h < 2; h++) {
                int o = m_blk + i * 16 + (lane >> 2) + h * 8;
                float bv = bias[o];
                float v0 = acc[i][j][h * 2 + 0] + bv;
                float v1 = acc[i][j][h * 2 + 1] + bv;
                if (ACT == 1) { v0 = silu_f(v0); v1 = silu_f(v1); }
                if (OUTFMT == 0) {
                    float2 ov; ov.x = v0; ov.y = v1;
                    *(float2*)(Y + ((size_t)b * CC + o) * S + s0 + c) = ov;
                } else {
                    __half q0 = __float2half_rn(v0);
                    __half q1 = __float2half_rn(v1);
                    trans[c * TPH + o] = *(u16*)&q0;
                    trans[(c + 1) * TPH + o] = *(u16*)&q1;
                }
            }
        }
    }
    if (OUTFMT == 1) {
        __syncthreads();
        u16* thi = tout + tb;
        #pragma unroll
        for (int it = 0; it < 8; it++) {
            int idx = tid + it * 256;
            int s = idx >> 4, c0 = (idx & 15) * 8;
            uint4 w = *(const uint4*)(trans + s * TPH + c0);
            *(uint4*)(thi + s * 128 + c0) = w;
        }
    }
}

// ================= dual-A GEMM, tile input =================
#define D2_A0 0
#define D2_A1 TILE_B
#define D2_B  (2*TILE_B)
#define D2_SMEM (3*TILE_B)

__global__ __launch_bounds__(256)
void gemm_dual(const u16* __restrict__ w0sc, const u16* __restrict__ w1sc,
               const float* __restrict__ bias0, const float* __restrict__ bias1,
               const u16* __restrict__ tin,
               float* __restrict__ Y0, float* __restrict__ Y1, int S)
{
    extern __shared__ char sm[];
    u32 sb = smem_u32(sm);
    int tid = threadIdx.x;
    int wid = tid >> 5, lane = tid & 31;
    int b  = blockIdx.y;
    int s0 = blockIdx.x * 128;
    size_t tb = ((size_t)(b * gridDim.x + blockIdx.x)) * 16384;

    stage_tile(sb + D2_A0, w0sc, tid);
    stage_tile(sb + D2_A1, w1sc, tid);
    stage_tile(sb + D2_B,  tin + tb, tid);
    CP_COMMIT();

    int m_blk = (wid & 3) * 32;
    int n_blk = (wid >> 2) * 64;
    float acc0[2][8][4], acc1[2][8][4];
    #pragma unroll
    for (int i = 0; i < 2; i++)
        #pragma unroll
        for (int j = 0; j < 8; j++)
            #pragma unroll
            for (int q = 0; q < 4; q++) { acc0[i][j][q] = 0.f; acc1[i][j][q] = 0.f; }

    u32 a_row = (u32)(m_blk + (lane & 15));
    u32 a_koff = (u32)((lane >> 4) << 3);
    u32 b_row = (u32)((lane & 7) + ((lane >> 4) << 3));
    u32 b_koff = (u32)(((lane >> 3) & 1) << 3);

    CP_WAIT0(); __syncthreads();
    mm_pass2(sb + D2_A0, sb + D2_A1, sb + D2_B, acc0, acc1,
             a_row, a_koff, b_row, b_koff, n_blk);

    #pragma unroll
    for (int i = 0; i < 2; i++) {
        #pragma unroll
        for (int j = 0; j < 8; j++) {
            int c = n_blk + j * 8 + (lane & 3) * 2;
            #pragma unroll
            for (int h = 0; h < 2; h++) {
                int o = m_blk + i * 16 + (lane >> 2) + h * 8;
                float2 o0, o1;
                o0.x = acc0[i][j][h * 2 + 0] + bias0[o];
                o0.y = acc0[i][j][h * 2 + 1] + bias0[o];
                o1.x = acc1[i][j][h * 2 + 0] + bias1[o];
                o1.y = acc1[i][j][h * 2 + 1] + bias1[o];
                *(float2*)(Y0 + ((size_t)b * CC + o) * S + s0 + c) = o0;
                *(float2*)(Y1 + ((size_t)b * CC + o) * S + s0 + c) = o1;
            }
        }
    }
}

// ================= single-A GEMM, tile input (ffn_out) =================
template<int EPI>
__global__ __launch_bounds__(256, 2)
void gemm_t16(const u16* __restrict__ wsc, const float* __restrict__ bias,
              const u16* __restrict__ tin, float* __restrict__ Y, int S)
{
    extern __shared__ char sm[];
    u32 sb = smem_u32(sm);
    int tid = threadIdx.x;
    int wid = tid >> 5, lane = tid & 31;
    int b  = blockIdx.y;
    int s0 = blockIdx.x * 128;
    size_t tb = ((size_t)(b * gridDim.x + blockIdx.x)) * 16384;

    stage_tile(sb + T16_A, wsc, tid);
    stage_tile(sb + T16_B, tin + tb, tid);
    CP_COMMIT();

    int m_blk = (wid & 3) * 32;
    int n_blk = (wid >> 2) * 64;
    float acc[2][8][4];
    #pragma unroll
    for (int i = 0; i < 2; i++)
        #pragma unroll
        for (int j = 0; j < 8; j++)
            #pragma unroll
            for (int q = 0; q < 4; q++) acc[i][j][q] = 0.f;

    u32 a_row = (u32)(m_blk + (lane & 15));
    u32 a_koff = (u32)((lane >> 4) << 3);
    u32 b_row = (u32)((lane & 7) + ((lane >> 4) << 3));
    u32 b_koff = (u32)(((lane >> 3) & 1) << 3);

    CP_WAIT0(); __syncthreads();
    mm_pass(sb + T16_A, sb + T16_B, acc, a_row, a_koff, b_row, b_koff, n_blk);

    #pragma unroll
    for (int i = 0; i < 2; i++) {
        #pragma unroll
        for (int j = 0; j < 8; j++) {
            int c = n_blk + j * 8 + (lane & 3) * 2;
            #pragma unroll
            for (int h = 0; h < 2; h++) {
                int o = m_blk + i * 16 + (lane >> 2) + h * 8;
                float bv = bias[o];
                float v0 = acc[i][j][h * 2 + 0] + bv;
                float v1 = acc[i][j][h * 2 + 1] + bv;
                float* yp = Y + ((size_t)b * CC + o) * S + s0 + c;
                if (EPI == 2) { v0 += yp[0]; v1 += yp[1]; }
                float2 ov; ov.x = v0; ov.y = v1;
                *(float2*)yp = ov;
            }
        }
    }
}

// ================= GLU with fused inv-rms, shared-bf dual pass =================
#define GL_AA 0
#define GL_AG TILE_B
#define GL_B  (2*TILE_B)
#define GL_SMEM (3*TILE_B + 512)

__global__ __launch_bounds__(256)
void glu_f16(const float* __restrict__ X, const u16* __restrict__ wsc,
             const float* __restrict__ bias, u16* __restrict__ tout, int S)
{
    extern __shared__ char sm[];
    u32 sb = smem_u32(sm);
    float* ssq = (float*)(sm + 3 * TILE_B);
    int tid = threadIdx.x;
    int wid = tid >> 5, lane = tid & 31;
    int b  = blockIdx.y;
    int s0 = blockIdx.x * 128;
    size_t tb = ((size_t)(b * gridDim.x + blockIdx.x)) * 16384;
    const float* Xb = X + (size_t)b * CC * S;

    if (tid < 128) ssq[tid] = 0.f;
    stage_tile(sb + GL_AA, wsc, tid);
    stage_tile(sb + GL_AG, wsc + 16384, tid);
    CP_COMMIT();
    __syncthreads();

    float local[4] = {0.f, 0.f, 0.f, 0.f};
    #pragma unroll
    for (int i = 0; i < 16; i++) {
        int s = lane + (i & 3) * 32;
        int c0 = ((wid << 2) + (i >> 2)) * 4;
        float4 x4;
        x4.x = Xb[(size_t)(c0 + 0) * S + s0 + s];
        x4.y = Xb[(size_t)(c0 + 1) * S + s0 + s];
        x4.z = Xb[(size_t)(c0 + 2) * S + s0 + s];
        x4.w = Xb[(size_t)(c0 + 3) * S + s0 + s];
        local[i & 3] += x4.x * x4.x + x4.y * x4.y + x4.z * x4.z + x4.w * x4.w;
    }
    #pragma unroll
    for (int j = 0; j < 4; j++)
        atomicAdd(&ssq[lane + j * 32], local[j]);
    __syncthreads();
    float rv[4];
    #pragma unroll
    for (int j = 0; j < 4; j++)
        rv[j] = rsqrtf(ssq[lane + j * 32] * (1.0f / CC) + 1e-6f);

    #pragma unroll
    for (int i = 0; i < 16; i++) {
        int s = lane + (i & 3) * 32;
        int c0 = ((wid << 2) + (i >> 2)) * 4;
        float4 x4;
        x4.x = Xb[(size_t)(c0 + 0) * S + s0 + s];
        x4.y = Xb[(size_t)(c0 + 1) * S + s0 + s];
        x4.z = Xb[(size_t)(c0 + 2) * S + s0 + s];
        x4.w = Xb[(size_t)(c0 + 3) * S + s0 + s];
        float r = rv[i & 3];
        x4.x *= r; x4.y *= r; x4.z *= r; x4.w *= r;
        cvt_store4h(sm, GL_B, s, c0, x4);
    }
    CP_WAIT0();
    __syncthreads();

    int m_blk = (wid & 3) * 32;
    int n_blk = (wid >> 2) * 64;
    float acca[2][8][4], accg[2][8][4];
    #pragma unroll
    for (int i = 0; i < 2; i++)
        #pragma unroll
        for (int j = 0; j < 8; j++)
            #pragma unroll
            for (int q = 0; q < 4; q++) { acca[i][j][q] = 0.f; accg[i][j][q] = 0.f; }

    u32 a_row = (u32)(m_blk + (lane & 15));
    u32 a_koff = (u32)((lane >> 4) << 3);
    u32 b_row = (u32)((lane & 7) + ((lane >> 4) << 3));
    u32 b_koff = (u32)(((lane >> 3) & 1) << 3);

    mm_pass2(sb + GL_AA, sb + GL_AG, sb + GL_B, acca, accg,
             a_row, a_koff, b_row, b_koff, n_blk);

    u16* trans = (u16*)sm;
    __syncthreads();
    #pragma unroll
    for (int i = 0; i < 2; i++) {
        #pragma unroll
        for (int j = 0; j < 8; j++) {
            int c = n_blk + j * 8 + (lane & 3) * 2;
            #pragma unroll
            for (int h = 0; h < 2; h++) {
                int o = m_blk + i * 16 + (lane >> 2) + h * 8;
                float ba = bias[o], bg = bias[CC + o];
                float v0 = (acca[i][j][h * 2 + 0] + ba) * silu_f(accg[i][j][h * 2 + 0] + bg);
                float v1 = (acca[i][j][h * 2 + 1] + ba) * silu_f(accg[i][j][h * 2 + 1] + bg);
                __half q0 = __float2half_rn(v0);
                __half q1 = __float2half_rn(v1);
                trans[c * TPH + o] = *(u16*)&q0;
                trans[(c + 1) * TPH + o] = *(u16*)&q1;
            }
        }
    }
    __syncthreads();
    {
        u16* thi = tout + tb;
        #pragma unroll
        for (int it = 0; it < 8; it++) {
            int idx = tid + it * 256;
            int s = idx >> 4, c0 = (idx & 15) * 8;
            uint4 w = *(const uint4*)(trans + s * TPH + c0);
            *(uint4*)(thi + s * 128 + c0) = w;
        }
    }
}

// ---------------- Attention + fused o-proj + query-skip ----------------
// smem: [0, 36864)            Ks (fp32 [128c][72])  -> later att_t fp16 [128f][TSTR]
//       [36864, 36864+69632)  Qs (fp32 [128][128])  -> later Vt + Wsm
//       [106496, 106496+34816) o_w fp16 tile
#define ATT_OW_OFF 106496
#define ATT_SMEM_BYTES (106496 + TILE_B)

__global__ __launch_bounds__(256)
void attn_kernel(const float* __restrict__ q, const float* __restrict__ kmat,
                 const float* __restrict__ vmat, const float* __restrict__ basis,
                 const float* __restrict__ ss_p, const float* __restrict__ ps_p,
                 const u16* __restrict__ owsc, const float* __restrict__ ob,
                 const float* __restrict__ qskip_p, const float* __restrict__ query_h,
                 float* __restrict__ out)
{
    extern __shared__ char smb[];
    float* smf = (float*)smb;
    float* Ks  = smf;
    float* Qs  = smf + 128 * 72;
    float* Vt  = Qs;
    float* Wsm = Qs + 64 * 136;
    u32 sb = smem_u32(smb);

    int fb = blockIdx.x * 128;
    int t  = blockIdx.y;
    int b  = blockIdx.z;
    int tid = threadIdx.x;
    int wid = tid >> 5, lane = tid & 31;
    int tx = tid & 15, ty = tid >> 4;

    stage_tile(sb + ATT_OW_OFF, owsc, tid);   // o_w fp16
    CP_COMMIT();

    const float* kb = kmat + (size_t)b * CC * S_LAT + t * KK;
    #pragma unroll
    for (int it = 0; it < 8; it++) {
        int idx = tid + it * 256;
        int c = idx >> 4, kq = idx & 15;
        float4 v = *(const float4*)(kb + (size_t)c * S_LAT + kq * 4);
        *(float4*)&Ks[c * 72 + kq * 4] = v;
    }
    const float* qb = q + (size_t)b * CC * S_SIDE + t * FF + fb;
    #pragma unroll
    for (int it = 0; it < 16; it++) {
        int idx = tid + it * 256;
        int c = idx >> 5, fq = idx & 31;
        float4 v = *(const float4*)(qb + (size_t)c * S_SIDE + fq * 4);
        *(float4*)&Qs[c * 128 + fq * 4] = v;
    }
    __syncthreads();

    // phase 1: scores [128f][64k]
    u64 sc2[8][2];
    #pragma unroll
    for (int i = 0; i < 8; i++) { sc2[i][0] = 0ull; sc2[i][1] = 0ull; }

    #pragma unroll 4
    for (int c = 0; c < CC; c++) {
        u64 kp0 = *(const u64*)&Ks[c * 72 + tx * 4];
        u64 kp1 = *(const u64*)&Ks[c * 72 + tx * 4 + 2];
        float4 q0 = *(const float4*)&Qs[c * 128 + ty * 8];
        float4 q1 = *(const float4*)&Qs[c * 128 + ty * 8 + 4];
        u64 qd[8] = {dup2(q0.x),dup2(q0.y),dup2(q0.z),dup2(q0.w),
                     dup2(q1.x),dup2(q1.y),dup2(q1.z),dup2(q1.w)};
        #pragma unroll
        for (int i = 0; i < 8; i++) {
            fma2(sc2[i][0], qd[i], kp0);
            fma2(sc2[i][1], qd[i], kp1);
        }
    }
    float sc[8][4];
    #pragma unroll
    for (int i = 0; i < 8; i++) {
        float2 p0 = unpack2(sc2[i][0]);
        float2 p1 = unpack2(sc2[i][1]);
        sc[i][0] = p0.x; sc[i][1] = p0.y; sc[i][2] = p1.x; sc[i][3] = p1.y;
    }
    float ssv = *ss_p, psv = *ps_p;
    #pragma unroll
    for (int i = 0; i < 8; i++)
        #pragma unroll
        for (int j = 0; j < 4; j++)
            sc[i][j] = sc[i][j] * ssv
                     + basis[(tx * 4 + j) * FF + fb + ty * 8 + i] * psv;
    __syncthreads();

    // softmax over k
    float w[8][4];
    #pragma unroll
    for (int i = 0; i < 8; i++) {
        float m = fmaxf(fmaxf(sc[i][0], sc[i][1]), fmaxf(sc[i][2], sc[i][3]));
        #pragma unroll
        for (int off = 8; off >= 1; off >>= 1)
            m = fmaxf(m, __shfl_xor_sync(0xffffffffu, m, off));
        float e0 = __expf(sc[i][0] - m);
        float e1 = __expf(sc[i][1] - m);
        float e2 = __expf(sc[i][2] - m);
        float e3 = __expf(sc[i][3] - m);
        float s = e0 + e1 + e2 + e3;
        #pragma unroll
        for (int off = 8; off >= 1; off >>= 1)
            s += __shfl_xor_sync(0xffffffffu, s, off);
        float inv = 1.0f / s;
        w[i][0] = e0 * inv; w[i][1] = e1 * inv;
        w[i][2] = e2 * inv; w[i][3] = e3 * inv;
    }
    #pragma unroll
    for (int i = 0; i < 8; i++)
        #pragma unroll
        for (int j = 0; j < 4; j++)
            Wsm[(tx * 4 + j) * 136 + ty * 8 + i] = w[i][j];

    const float* vb = vmat + (size_t)b * CC * S_LAT + t * KK;
    #pragma unroll
    for (int it = 0; it < 8; it++) {
        int idx = tid + it * 256;
        int c = idx >> 4, kq = idx & 15;
        float4 v = *(const float4*)(vb + (size_t)c * S_LAT + kq * 4);
        Vt[(kq * 4 + 0) * 136 + c] = v.x;
        Vt[(kq * 4 + 1) * 136 + c] = v.y;
        Vt[(kq * 4 + 2) * 136 + c] = v.z;
        Vt[(kq * 4 + 3) * 136 + c] = v.w;
    }
    __syncthreads();

    // phase 2: att tile [128c][128f]
    u64 ac2[4][8];
    #pragma unroll
    for (int i = 0; i < 4; i++)
        #pragma unroll
        for (int j = 0; j < 8; j++) ac2[i][j] = 0ull;

    #pragma unroll 4
    for (int k = 0; k < KK; k++) {
        u64 vp[4];
        #pragma unroll
        for (int i = 0; i < 4; i++)
            vp[i] = *(const u64*)&Vt[k * 136 + ty * 8 + 2 * i];
        float4 w0 = *(const float4*)&Wsm[k * 136 + tx * 8];
        float4 w1 = *(const float4*)&Wsm[k * 136 + tx * 8 + 4];
        u64 wd[8] = {dup2(w0.x),dup2(w0.y),dup2(w0.z),dup2(w0.w),
                     dup2(w1.x),dup2(w1.y),dup2(w1.z),dup2(w1.w)};
        #pragma unroll
        for (int i = 0; i < 4; i++)
            #pragma unroll
            for (int j = 0; j < 8; j++)
                fma2(ac2[i][j], vp[i], wd[j]);
    }

    // convert att tile to fp16 att_t [f-row][c-col] over the dead Ks region
    #pragma unroll
    for (int i = 0; i < 4; i++) {
        int c0 = ty * 8 + 2 * i;
        #pragma unroll
        for (int j = 0; j < 8; j++) {
            int f = tx * 8 + j;
            float2 p = unpack2(ac2[i][j]);
            __half h0 = __float2half_rn(p.x);
            __half h1 = __float2half_rn(p.y);
            u32 pk = (u32)*(u16*)&h0 | ((u32)*(u16*)&h1 << 16);
            *(u32*)(smb + f * TSTR + c0 * 2) = pk;
        }
    }
    __syncthreads();
    CP_WAIT0();

    // o-proj HMMA: hidden[o, f] = sum_c o_w[o,c] * att_t[f,c]
    {
        int m_blk = (wid & 3) * 32;
        int n_blk = (wid >> 2) * 64;
        float acc[2][8][4];
        #pragma unroll
        for (int i = 0; i < 2; i++)
            #pragma unroll
            for (int j = 0; j < 8; j++)
                #pragma unroll
                for (int qd = 0; qd < 4; qd++) acc[i][j][qd] = 0.f;

        u32 a_row = (u32)(m_blk + (lane & 15));
        u32 a_koff = (u32)((lane >> 4) << 3);
        u32 b_row = (u32)((lane & 7) + ((lane >> 4) << 3));
        u32 b_koff = (u32)(((lane >> 3) & 1) << 3);

        mm_pass(sb + ATT_OW_OFF, sb, acc, a_row, a_koff, b_row, b_koff, n_blk);

        float qss = *qskip_p;
        #pragma unroll
        for (int i = 0; i < 2; i++) {
            #pragma unroll
            for (int j = 0; j < 8; j++) {
                int f = n_blk + j * 8 + (lane & 3) * 2;
                #pragma unroll
                for (int h = 0; h < 2; h++) {
                    int o = m_blk + i * 16 + (lane >> 2) + h * 8;
                    size_t base = ((size_t)b * CC + o) * S_SIDE + t * FF + fb + f;
                    float2 qh = *(const float2*)(query_h + base);
                    float2 ov;
                    ov.x = acc[i][j][h * 2 + 0] + ob[o] + qss * qh.x;
                    ov.y = acc[i][j][h * 2 + 1] + ob[o] + qss * qh.y;
                    *(float2*)(out + base) = ov;
                }
            }
        }
    }
}

// ---------------- host ----------------
extern "C" void kernel_launch(void* const* d_in, const int* in_sizes, int n_in,
                              void* d_out, int out_size)
{
    const float* latent     = (const float*)d_in[0];
    const float* side       = (const float*)d_in[1];
    const float* basis      = (const float*)d_in[2];
    const float* lp_gamma   = (const float*)d_in[3];
    const float* lp_w       = (const float*)d_in[4];
    const float* lp_b       = (const float*)d_in[5];
    const float* qn_gamma   = (const float*)d_in[6];
    const float* qmlp_in_w  = (const float*)d_in[7];
    const float* qmlp_in_b  = (const float*)d_in[8];
    const float* qmlp_out_w = (const float*)d_in[9];
    const float* qmlp_out_b = (const float*)d_in[10];
    const float* q_w        = (const float*)d_in[11];
    const float* q_b        = (const float*)d_in[12];
    const float* k_w        = (const float*)d_in[13];
    const float* k_b        = (const float*)d_in[14];
    const float* v_w        = (const float*)d_in[15];
    const float* v_b        = (const float*)d_in[16];
    const float* o_w        = (const float*)d_in[17];
    const float* o_b        = (const float*)d_in[18];
    const float* ffn_gamma  = (const float*)d_in[19];
    const float* ffn_in_w   = (const float*)d_in[20];
    const float* ffn_in_b   = (const float*)d_in[21];
    const float* ffn_out_w  = (const float*)d_in[22];
    const float* ffn_out_b  = (const float*)d_in[23];
    const float* score_sc   = (const float*)d_in[24];
    const float* prior_sc   = (const float*)d_in[25];
    const float* qskip_sc   = (const float*)d_in[26];
    float* out = (float*)d_out;

    float *buf2, *buf3, *kmat, *vmat, *qbias;
    u16 *tA, *tL, *wbf;
    cudaGetSymbolAddress((void**)&buf2, g_buf2);
    cudaGetSymbolAddress((void**)&buf3, g_buf3);
    cudaGetSymbolAddress((void**)&kmat, g_k);
    cudaGetSymbolAddress((void**)&vmat, g_v);
    cudaGetSymbolAddress((void**)&qbias, g_qbias);
    cudaGetSymbolAddress((void**)&tA,   g_tA);
    cudaGetSymbolAddress((void**)&tL,   g_tL);
    cudaGetSymbolAddress((void**)&wbf,  g_wbf);

    cudaFuncSetAttribute(attn_kernel, cudaFuncAttributeMaxDynamicSharedMemorySize, ATT_SMEM_BYTES);
    cudaFuncSetAttribute(gemm_f16in<1,1,1>, cudaFuncAttributeMaxDynamicSharedMemorySize, T16_SMEM);
    cudaFuncSetAttribute(gemm_dual, cudaFuncAttributeMaxDynamicSharedMemorySize, D2_SMEM);
    cudaFuncSetAttribute(gemm_t16<2>, cudaFuncAttributeMaxDynamicSharedMemorySize, T16_SMEM);
    cudaFuncSetAttribute(glu_f16, cudaFuncAttributeMaxDynamicSharedMemorySize, GL_SMEM);

    dim3 blk(256);

    // 0: fused weight pre-convert + q-fold
    convert_all<<<704, blk>>>(lp_w, k_w, v_w, qmlp_out_w, o_w, ffn_out_w,
                              qmlp_in_w, ffn_in_w, lp_gamma, qn_gamma, ffn_gamma,
                              q_w, qmlp_out_b, q_b, wbf, qbias);

    // 1: glu1 (fused rms)
    glu_f16<<<dim3(S_SIDE/128, BB), blk, GL_SMEM>>>(side, wbf + WQI, qmlp_in_b, tA, S_SIDE);

    // 2: latent_pre (fused rms, tile out)
    gemm_f16in<1,1,1><<<dim3(S_LAT/128, BB), blk, T16_SMEM>>>(
        latent, wbf + WLP, lp_b, nullptr, tL, S_LAT);

    // 3: merged qmlp_out + q
    gemm_dual<<<dim3(S_SIDE/128, BB), blk, D2_SMEM>>>(
        wbf + WQO, wbf + WQF, qmlp_out_b, qbias, tA, buf3, buf2, S_SIDE);

    // 4: merged k + v
    gemm_dual<<<dim3(S_LAT/128, BB), blk, D2_SMEM>>>(
        wbf + WK, wbf + WV, k_b, v_b, tL, kmat, vmat, S_LAT);

    // 5: attention + fused o-proj + skip — PROFILED SLOT
    attn_kernel<<<dim3(FF/128, TT, BB), blk, ATT_SMEM_BYTES>>>(
        buf2, kmat, vmat, basis, score_sc, prior_sc,
        wbf + WO, o_b, qskip_sc, buf3, out);

    // 6: glu2 (fused rms on `out`)
    glu_f16<<<dim3(S_SIDE/128, BB), blk, GL_SMEM>>>(out, wbf + WFI, ffn_in_b, tA, S_SIDE);

    // 7: ffn_out (residual into out)
    gemm_t16<2><<<dim3(S_SIDE/128, BB), blk, T16_SMEM>>>(
        wbf + WFO, ffn_out_b, tA, out, S_SIDE);
}

// round 17
// speedup vs baseline: 1.0492x; 1.0492x over previous
#include <cuda_runtime.h>
#include <cuda_fp16.h>
#include <cstdint>

#define BB 8
#define CC 128
#define TT 128
#define FF 512
#define KK 64
#define S_SIDE (TT*FF)
#define S_LAT  (TT*KK)

typedef unsigned long long u64;
typedef unsigned int u32;
typedef unsigned short u16;

// ---------------- scratch ----------------
__device__ float g_buf2[BB*CC*S_SIDE];            // q (fp32)
__device__ float g_buf3[BB*CC*S_SIDE];            // query_h (fp32, for skip)
__device__ float g_k  [BB*CC*S_LAT];
__device__ float g_v  [BB*CC*S_LAT];
__device__ float g_qbias[CC];                     // folded q bias

// fp16 tile buffers: per (b,tile128): 16384 u16
__device__ u16 g_tA[8*512*16384];                 // glu out / att tile (reused)
__device__ u16 g_tL[8*64*16384];                  // latent_h

// pre-converted fp16 weights
#define WLP 0
#define WK  16384
#define WV  32768
#define WQO 49152
#define WO  65536
#define WFO 81920
#define WQI 98304
#define WFI 131072
#define WQF 163840
__device__ u16 g_wbf[180224];

__device__ __forceinline__ float silu_f(float x) { return x / (1.0f + __expf(-x)); }
__device__ __forceinline__ u64 dup2(float v) {
    u64 r; asm("mov.b64 %0, {%1, %2};" : "=l"(r) : "f"(v), "f"(v)); return r;
}
__device__ __forceinline__ void fma2(u64& d, u64 a, u64 b) {
    asm("fma.rn.f32x2 %0, %1, %2, %0;" : "+l"(d) : "l"(a), "l"(b));
}
__device__ __forceinline__ float2 unpack2(u64 v) {
    float2 r; asm("mov.b64 {%0, %1}, %2;" : "=f"(r.x), "=f"(r.y) : "l"(v)); return r;
}
__device__ __forceinline__ u32 smem_u32(const void* p) {
    u32 a;
    asm("{ .reg .u64 t; cvta.to.shared.u64 t, %1; cvt.u32.u64 %0, t; }" : "=r"(a) : "l"(p));
    return a;
}

// ---------------- mma.sync helpers (fp16) ----------------
__device__ __forceinline__ void ldsm4(u32* r, u32 addr) {
    asm volatile("ldmatrix.sync.aligned.m8n8.x4.shared.b16 {%0,%1,%2,%3}, [%4];"
                 : "=r"(r[0]), "=r"(r[1]), "=r"(r[2]), "=r"(r[3]) : "r"(addr));
}
__device__ __forceinline__ void mma16816(float* d, const u32* a, const u32* b) {
    asm volatile("mma.sync.aligned.m16n8k16.row.col.f32.f16.f16.f32 "
                 "{%0,%1,%2,%3}, {%4,%5,%6,%7}, {%8,%9}, {%0,%1,%2,%3};"
                 : "+f"(d[0]), "+f"(d[1]), "+f"(d[2]), "+f"(d[3])
                 : "r"(a[0]), "r"(a[1]), "r"(a[2]), "r"(a[3]), "r"(b[0]), "r"(b[1]));
}
__device__ __forceinline__ void cpa16(u32 saddr, const void* g) {
    asm volatile("cp.async.cg.shared.global [%0], [%1], 16;" :: "r"(saddr), "l"(g));
}
#define CP_COMMIT() asm volatile("cp.async.commit_group;" ::: "memory")
#define CP_WAIT0()  asm volatile("cp.async.wait_group 0;" ::: "memory")

#define TSTR  272
#define TILE_B (128*TSTR)
#define TPH 136

__device__ __forceinline__ void cvt_store4h(char* smem, u32 base, int row, int col, float4 x) {
    __half h0 = __float2half_rn(x.x);
    __half h1 = __float2half_rn(x.y);
    __half h2 = __float2half_rn(x.z);
    __half h3 = __float2half_rn(x.w);
    u64 hv = (u64)*(u16*)&h0 | ((u64)*(u16*)&h1 << 16) | ((u64)*(u16*)&h2 << 32) | ((u64)*(u16*)&h3 << 48);
    *(u64*)(smem + base + (u32)(row * TSTR + col * 2)) = hv;
}

__device__ __forceinline__ void stage_tile(u32 sbase, const u16* g, int tid) {
    #pragma unroll
    for (int it = 0; it < 8; it++) {
        int idx = tid + it * 256;
        int r = idx >> 4, ch = idx & 15;
        cpa16(sbase + r * TSTR + ch * 16, g + r * 128 + ch * 8);
    }
}

// single-A k-loop; warp covers 32m x 64n
__device__ __forceinline__ void mm_pass(u32 ab, u32 bb, float (*acc)[8][4],
                                        u32 a_row, u32 a_koff, u32 b_row, u32 b_koff,
                                        int n_blk)
{
    #pragma unroll
    for (int ks = 0; ks < 8; ks++) {
        int k0 = ks * 16;
        u32 af[2][4], bf[4][4];
        #pragma unroll
        for (int i = 0; i < 2; i++)
            ldsm4(af[i], ab + (a_row + i * 16) * TSTR + (k0 + a_koff) * 2);
        #pragma unroll
        for (int j = 0; j < 4; j++)
            ldsm4(bf[j], bb + (n_blk + j * 16 + b_row) * TSTR + (k0 + b_koff) * 2);
        #pragma unroll
        for (int i = 0; i < 2; i++)
            #pragma unroll
            for (int j = 0; j < 8; j++)
                mma16816(acc[i][j], af[i], &bf[j >> 1][(j & 1) * 2]);
    }
}

// dual-A k-loop: bf loaded once for both A tiles
__device__ __forceinline__ void mm_pass2(u32 a0, u32 a1, u32 bb,
                                         float (*acc0)[8][4], float (*acc1)[8][4],
                                         u32 a_row, u32 a_koff, u32 b_row, u32 b_koff,
                                         int n_blk)
{
    #pragma unroll
    for (int ks = 0; ks < 8; ks++) {
        int k0 = ks * 16;
        u32 af0[2][4], af1[2][4], bf[4][4];
        #pragma unroll
        for (int i = 0; i < 2; i++) {
            ldsm4(af0[i], a0 + (a_row + i * 16) * TSTR + (k0 + a_koff) * 2);
            ldsm4(af1[i], a1 + (a_row + i * 16) * TSTR + (k0 + a_koff) * 2);
        }
        #pragma unroll
        for (int j = 0; j < 4; j++)
            ldsm4(bf[j], bb + (n_blk + j * 16 + b_row) * TSTR + (k0 + b_koff) * 2);
        #pragma unroll
        for (int i = 0; i < 2; i++)
            #pragma unroll
            for (int j = 0; j < 8; j++) {
                mma16816(acc0[i][j], af0[i], &bf[j >> 1][(j & 1) * 2]);
                mma16816(acc1[i][j], af1[i], &bf[j >> 1][(j & 1) * 2]);
            }
    }
}

// ---------------- fused weight pre-convert + q-fold ----------------
__global__ __launch_bounds__(256)
void convert_all(const float* __restrict__ lp_w, const float* __restrict__ k_w,
                 const float* __restrict__ v_w,  const float* __restrict__ qo_w,
                 const float* __restrict__ o_w,  const float* __restrict__ fo_w,
                 const float* __restrict__ qi_w, const float* __restrict__ fi_w,
                 const float* __restrict__ lp_g, const float* __restrict__ qn_g,
                 const float* __restrict__ ffn_g,
                 const float* __restrict__ qw, const float* __restrict__ qob,
                 const float* __restrict__ qb,
                 u16* __restrict__ dst, float* __restrict__ qbias)
{
    int bid = blockIdx.x;
    if (bid >= 640) {   // q-fold blocks: 640..703
        int idx = (bid - 640) * 256 + threadIdx.x;
        int o = idx >> 7, c = idx & 127;
        float s = 0.f;
        #pragma unroll 4
        for (int m = 0; m < 128; m++)
            s += qw[o * 128 + m] * qo_w[m * 128 + c];
        __half h = __float2half_rn(s);
        dst[WQF + idx] = *(u16*)&h;
        if (c == 0) {
            float t = qb[o];
            #pragma unroll 4
            for (int m = 0; m < 128; m++)
                t += qw[o * 128 + m] * qob[m];
            qbias[o] = t;
        }
        return;
    }
    const float* src; const float* gamma = nullptr; int off, n, lb;
    if (bid < 384) {
        int seg = bid >> 6; lb = bid & 63; n = 16384;
        switch (seg) {
            case 0: src = lp_w; gamma = lp_g; off = WLP; break;
            case 1: src = k_w;  off = WK;  break;
            case 2: src = v_w;  off = WV;  break;
            case 3: src = qo_w; off = WQO; break;
            case 4: src = o_w;  off = WO;  break;
            default: src = fo_w; off = WFO; break;
        }
    } else if (bid < 512) {
        lb = bid - 384; src = qi_w; gamma = qn_g; off = WQI; n = 32768;
    } else {
        lb = bid - 512; src = fi_w; gamma = ffn_g; off = WFI; n = 32768;
    }
    int idx = lb * 256 + threadIdx.x;
    if (idx >= n) return;
    float v = src[idx];
    if (gamma) v *= gamma[idx & 127];
    __half h = __float2half_rn(v);
    dst[off + idx] = *(u16*)&h;
}

// ================= fp16 GEMM, fp32 input, fused inv-rms =================
#define T16_A 0
#define T16_B TILE_B
#define T16_SMEM (2*TILE_B + 512)

template<int NORM, int ACT, int OUTFMT>
__global__ __launch_bounds__(256, 2)
void gemm_f16in(const float* __restrict__ X, const u16* __restrict__ wsc,
                const float* __restrict__ bias, float* __restrict__ Y,
                u16* __restrict__ tout, int S)
{
    extern __shared__ char sm[];
    u32 sb = smem_u32(sm);
    float* ssq = (float*)(sm + 2 * TILE_B);
    int tid = threadIdx.x;
    int wid = tid >> 5, lane = tid & 31;
    int b  = blockIdx.y;
    int s0 = blockIdx.x * 128;
    size_t tb = ((size_t)(b * gridDim.x + blockIdx.x)) * 16384;
    const float* Xb = X + (size_t)b * CC * S;

    if (NORM && tid < 128) ssq[tid] = 0.f;
    stage_tile(sb + T16_A, wsc, tid);
    CP_COMMIT();

    float rv[4] = {1.f, 1.f, 1.f, 1.f};
    if (NORM) {
        __syncthreads();
        float local[4] = {0.f, 0.f, 0.f, 0.f};
        #pragma unroll
        for (int i = 0; i < 16; i++) {
            int s = lane + (i & 3) * 32;
            int c0 = ((wid << 2) + (i >> 2)) * 4;
            float4 x4;
            x4.x = Xb[(size_t)(c0 + 0) * S + s0 + s];
            x4.y = Xb[(size_t)(c0 + 1) * S + s0 + s];
            x4.z = Xb[(size_t)(c0 + 2) * S + s0 + s];
            x4.w = Xb[(size_t)(c0 + 3) * S + s0 + s];
            local[i & 3] += x4.x * x4.x + x4.y * x4.y + x4.z * x4.z + x4.w * x4.w;
        }
        #pragma unroll
        for (int j = 0; j < 4; j++)
            atomicAdd(&ssq[lane + j * 32], local[j]);
        __syncthreads();
        #pragma unroll
        for (int j = 0; j < 4; j++)
            rv[j] = rsqrtf(ssq[lane + j * 32] * (1.0f / CC) + 1e-6f);
    }
    #pragma unroll
    for (int i = 0; i < 16; i++) {
        int s = lane + (i & 3) * 32;
        int c0 = ((wid << 2) + (i >> 2)) * 4;
        float4 x4;
        x4.x = Xb[(size_t)(c0 + 0) * S + s0 + s];
        x4.y = Xb[(size_t)(c0 + 1) * S + s0 + s];
        x4.z = Xb[(size_t)(c0 + 2) * S + s0 + s];
        x4.w = Xb[(size_t)(c0 + 3) * S + s0 + s];
        if (NORM) {
            float r = rv[i & 3];
            x4.x *= r; x4.y *= r; x4.z *= r; x4.w *= r;
        }
        cvt_store4h(sm, T16_B, s, c0, x4);
    }

    int m_blk = (wid & 3) * 32;
    int n_blk = (wid >> 2) * 64;
    float acc[2][8][4];
    #pragma unroll
    for (int i = 0; i < 2; i++)
        #pragma unroll
        for (int j = 0; j < 8; j++)
            #pragma unroll
            for (int q = 0; q < 4; q++) acc[i][j][q] = 0.f;

    u32 a_row = (u32)(m_blk + (lane & 15));
    u32 a_koff = (u32)((lane >> 4) << 3);
    u32 b_row = (u32)((lane & 7) + ((lane >> 4) << 3));
    u32 b_koff = (u32)(((lane >> 3) & 1) << 3);

    CP_WAIT0(); __syncthreads();
    mm_pass(sb + T16_A, sb + T16_B, acc, a_row, a_koff, b_row, b_koff, n_blk);

    u16* trans = (u16*)(sm + T16_B);
    if (OUTFMT == 1) __syncthreads();
    #pragma unroll
    for (int i = 0; i < 2; i++) {
        #pragma unroll
        for (int j = 0; j < 8; j++) {
            int c = n_blk + j * 8 + (lane & 3) * 2;
            #pragma unroll
            for (int h = 0; h < 2; h++) {
                int o = m_blk + i * 16 + (lane >> 2) + h * 8;
                float bv = bias[o];
                float v0 = acc[i][j][h * 2 + 0] + bv;
                float v1 = acc[i][j][h * 2 + 1] + bv;
                if (ACT == 1) { v0 = silu_f(v0); v1 = silu_f(v1); }
                if (OUTFMT == 0) {
                    float2 ov; ov.x = v0; ov.y = v1;
                    *(float2*)(Y + ((size_t)b * CC + o) * S + s0 + c) = ov;
                } else {
                    __half q0 = __float2half_rn(v0);
                    __half q1 = __float2half_rn(v1);
                    trans[c * TPH + o] = *(u16*)&q0;
                    trans[(c + 1) * TPH + o] = *(u16*)&q1;
                }
            }
        }
    }
    if (OUTFMT == 1) {
        __syncthreads();
        u16* thi = tout + tb;
        #pragma unroll
        for (int it = 0; it < 8; it++) {
            int idx = tid + it * 256;
            int s = idx >> 4, c0 = (idx & 15) * 8;
            uint4 w = *(const uint4*)(trans + s * TPH + c0);
            *(uint4*)(thi + s * 128 + c0) = w;
        }
    }
}

// ================= dual-A GEMM, tile input =================
#define D2_A0 0
#define D2_A1 TILE_B
#define D2_B  (2*TILE_B)
#define D2_SMEM (3*TILE_B)

__global__ __launch_bounds__(256)
void gemm_dual(const u16* __restrict__ w0sc, const u16* __restrict__ w1sc,
               const float* __restrict__ bias0, const float* __restrict__ bias1,
               const u16* __restrict__ tin,
               float* __restrict__ Y0, float* __restrict__ Y1, int S)
{
    extern __shared__ char sm[];
    u32 sb = smem_u32(sm);
    int tid = threadIdx.x;
    int wid = tid >> 5, lane = tid & 31;
    int b  = blockIdx.y;
    int s0 = blockIdx.x * 128;
    size_t tb = ((size_t)(b * gridDim.x + blockIdx.x)) * 16384;

    stage_tile(sb + D2_A0, w0sc, tid);
    stage_tile(sb + D2_A1, w1sc, tid);
    stage_tile(sb + D2_B,  tin + tb, tid);
    CP_COMMIT();

    int m_blk = (wid & 3) * 32;
    int n_blk = (wid >> 2) * 64;
    float acc0[2][8][4], acc1[2][8][4];
    #pragma unroll
    for (int i = 0; i < 2; i++)
        #pragma unroll
        for (int j = 0; j < 8; j++)
            #pragma unroll
            for (int q = 0; q < 4; q++) { acc0[i][j][q] = 0.f; acc1[i][j][q] = 0.f; }

    u32 a_row = (u32)(m_blk + (lane & 15));
    u32 a_koff = (u32)((lane >> 4) << 3);
    u32 b_row = (u32)((lane & 7) + ((lane >> 4) << 3));
    u32 b_koff = (u32)(((lane >> 3) & 1) << 3);

    CP_WAIT0(); __syncthreads();
    mm_pass2(sb + D2_A0, sb + D2_A1, sb + D2_B, acc0, acc1,
             a_row, a_koff, b_row, b_koff, n_blk);

    #pragma unroll
    for (int i = 0; i < 2; i++) {
        #pragma unroll
        for (int j = 0; j < 8; j++) {
            int c = n_blk + j * 8 + (lane & 3) * 2;
            #pragma unroll
            for (int h = 0; h < 2; h++) {
                int o = m_blk + i * 16 + (lane >> 2) + h * 8;
                float2 o0, o1;
                o0.x = acc0[i][j][h * 2 + 0] + bias0[o];
                o0.y = acc0[i][j][h * 2 + 1] + bias0[o];
                o1.x = acc1[i][j][h * 2 + 0] + bias1[o];
                o1.y = acc1[i][j][h * 2 + 1] + bias1[o];
                *(float2*)(Y0 + ((size_t)b * CC + o) * S + s0 + c) = o0;
                *(float2*)(Y1 + ((size_t)b * CC + o) * S + s0 + c) = o1;
            }
        }
    }
}

// ================= single-A GEMM, tile input =================
// EPI: 0 none, 1 +scl*extra, 2 += Y
template<int EPI>
__global__ __launch_bounds__(256, 2)
void gemm_t16(const u16* __restrict__ wsc, const float* __restrict__ bias,
              const u16* __restrict__ tin, float* __restrict__ Y,
              const float* __restrict__ extra, const float* __restrict__ sc_p, int S)
{
    extern __shared__ char sm[];
    u32 sb = smem_u32(sm);
    int tid = threadIdx.x;
    int wid = tid >> 5, lane = tid & 31;
    int b  = blockIdx.y;
    int s0 = blockIdx.x * 128;
    size_t tb = ((size_t)(b * gridDim.x + blockIdx.x)) * 16384;

    stage_tile(sb + T16_A, wsc, tid);
    stage_tile(sb + T16_B, tin + tb, tid);
    CP_COMMIT();

    int m_blk = (wid & 3) * 32;
    int n_blk = (wid >> 2) * 64;
    float acc[2][8][4];
    #pragma unroll
    for (int i = 0; i < 2; i++)
        #pragma unroll
        for (int j = 0; j < 8; j++)
            #pragma unroll
            for (int q = 0; q < 4; q++) acc[i][j][q] = 0.f;

    u32 a_row = (u32)(m_blk + (lane & 15));
    u32 a_koff = (u32)((lane >> 4) << 3);
    u32 b_row = (u32)((lane & 7) + ((lane >> 4) << 3));
    u32 b_koff = (u32)(((lane >> 3) & 1) << 3);

    CP_WAIT0(); __syncthreads();
    mm_pass(sb + T16_A, sb + T16_B, acc, a_row, a_koff, b_row, b_koff, n_blk);

    float scl = (EPI == 1) ? *sc_p : 0.f;
    #pragma unroll
    for (int i = 0; i < 2; i++) {
        #pragma unroll
        for (int j = 0; j < 8; j++) {
            int c = n_blk + j * 8 + (lane & 3) * 2;
            #pragma unroll
            for (int h = 0; h < 2; h++) {
                int o = m_blk + i * 16 + (lane >> 2) + h * 8;
                float bv = bias[o];
                float v0 = acc[i][j][h * 2 + 0] + bv;
                float v1 = acc[i][j][h * 2 + 1] + bv;
                float* yp = Y + ((size_t)b * CC + o) * S + s0 + c;
                if (EPI == 1) {
                    const float* ep = extra + ((size_t)b * CC + o) * S + s0 + c;
                    v0 += scl * ep[0]; v1 += scl * ep[1];
                }
                if (EPI == 2) { v0 += yp[0]; v1 += yp[1]; }
                float2 ov; ov.x = v0; ov.y = v1;
                *(float2*)yp = ov;
            }
        }
    }
}

// ================= GLU with fused inv-rms, shared-bf dual pass =================
#define GL_AA 0
#define GL_AG TILE_B
#define GL_B  (2*TILE_B)
#define GL_SMEM (3*TILE_B + 512)

__global__ __launch_bounds__(256)
void glu_f16(const float* __restrict__ X, const u16* __restrict__ wsc,
             const float* __restrict__ bias, u16* __restrict__ tout, int S)
{
    extern __shared__ char sm[];
    u32 sb = smem_u32(sm);
    float* ssq = (float*)(sm + 3 * TILE_B);
    int tid = threadIdx.x;
    int wid = tid >> 5, lane = tid & 31;
    int b  = blockIdx.y;
    int s0 = blockIdx.x * 128;
    size_t tb = ((size_t)(b * gridDim.x + blockIdx.x)) * 16384;
    const float* Xb = X + (size_t)b * CC * S;

    if (tid < 128) ssq[tid] = 0.f;
    stage_tile(sb + GL_AA, wsc, tid);
    stage_tile(sb + GL_AG, wsc + 16384, tid);
    CP_COMMIT();
    __syncthreads();

    float local[4] = {0.f, 0.f, 0.f, 0.f};
    #pragma unroll
    for (int i = 0; i < 16; i++) {
        int s = lane + (i & 3) * 32;
        int c0 = ((wid << 2) + (i >> 2)) * 4;
        float4 x4;
        x4.x = Xb[(size_t)(c0 + 0) * S + s0 + s];
        x4.y = Xb[(size_t)(c0 + 1) * S + s0 + s];
        x4.z = Xb[(size_t)(c0 + 2) * S + s0 + s];
        x4.w = Xb[(size_t)(c0 + 3) * S + s0 + s];
        local[i & 3] += x4.x * x4.x + x4.y * x4.y + x4.z * x4.z + x4.w * x4.w;
    }
    #pragma unroll
    for (int j = 0; j < 4; j++)
        atomicAdd(&ssq[lane + j * 32], local[j]);
    __syncthreads();
    float rv[4];
    #pragma unroll
    for (int j = 0; j < 4; j++)
        rv[j] = rsqrtf(ssq[lane + j * 32] * (1.0f / CC) + 1e-6f);

    #pragma unroll
    for (int i = 0; i < 16; i++) {
        int s = lane + (i & 3) * 32;
        int c0 = ((wid << 2) + (i >> 2)) * 4;
        float4 x4;
        x4.x = Xb[(size_t)(c0 + 0) * S + s0 + s];
        x4.y = Xb[(size_t)(c0 + 1) * S + s0 + s];
        x4.z = Xb[(size_t)(c0 + 2) * S + s0 + s];
        x4.w = Xb[(size_t)(c0 + 3) * S + s0 + s];
        float r = rv[i & 3];
        x4.x *= r; x4.y *= r; x4.z *= r; x4.w *= r;
        cvt_store4h(sm, GL_B, s, c0, x4);
    }
    CP_WAIT0();
    __syncthreads();

    int m_blk = (wid & 3) * 32;
    int n_blk = (wid >> 2) * 64;
    float acca[2][8][4], accg[2][8][4];
    #pragma unroll
    for (int i = 0; i < 2; i++)
        #pragma unroll
        for (int j = 0; j < 8; j++)
            #pragma unroll
            for (int q = 0; q < 4; q++) { acca[i][j][q] = 0.f; accg[i][j][q] = 0.f; }

    u32 a_row = (u32)(m_blk + (lane & 15));
    u32 a_koff = (u32)((lane >> 4) << 3);
    u32 b_row = (u32)((lane & 7) + ((lane >> 4) << 3));
    u32 b_koff = (u32)(((lane >> 3) & 1) << 3);

    mm_pass2(sb + GL_AA, sb + GL_AG, sb + GL_B, acca, accg,
             a_row, a_koff, b_row, b_koff, n_blk);

    u16* trans = (u16*)sm;
    __syncthreads();
    #pragma unroll
    for (int i = 0; i < 2; i++) {
        #pragma unroll
        for (int j = 0; j < 8; j++) {
            int c = n_blk + j * 8 + (lane & 3) * 2;
            #pragma unroll
            for (int h = 0; h < 2; h++) {
                int o = m_blk + i * 16 + (lane >> 2) + h * 8;
                float ba = bias[o], bg = bias[CC + o];
                float v0 = (acca[i][j][h * 2 + 0] + ba) * silu_f(accg[i][j][h * 2 + 0] + bg);
                float v1 = (acca[i][j][h * 2 + 1] + ba) * silu_f(accg[i][j][h * 2 + 1] + bg);
                __half q0 = __float2half_rn(v0);
                __half q1 = __float2half_rn(v1);
                trans[c * TPH + o] = *(u16*)&q0;
                trans[(c + 1) * TPH + o] = *(u16*)&q1;
            }
        }
    }
    __syncthreads();
    {
        u16* thi = tout + tb;
        #pragma unroll
        for (int it = 0; it < 8; it++) {
            int idx = tid + it * 256;
            int s = idx >> 4, c0 = (idx & 15) * 8;
            uint4 w = *(const uint4*)(trans + s * TPH + c0);
            *(uint4*)(thi + s * 128 + c0) = w;
        }
    }
}

// ---------------- Attention (SIMT fp32), fp16 tile output ----------------
#define ATT_SMEM_FLOATS (128*72 + 2*64*136)
#define ATT_SMEM_BYTES  (ATT_SMEM_FLOATS * 4)

__global__ __launch_bounds__(256)
void attn_kernel(const float* __restrict__ q, const float* __restrict__ kmat,
                 const float* __restrict__ vmat, const float* __restrict__ basis,
                 const float* __restrict__ ss_p, const float* __restrict__ ps_p,
                 u16* __restrict__ tout)
{
    extern __shared__ char smb[];
    float* smf = (float*)smb;
    float* Ks  = smf;
    float* Qs  = smf + 128 * 72;
    float* Vt  = Qs;
    float* Wsm = Qs + 64 * 136;

    int fb = blockIdx.x * 128;
    int t  = blockIdx.y;
    int b  = blockIdx.z;
    int tid = threadIdx.x;
    int tx = tid & 15, ty = tid >> 4;
    int tile = t * (FF / 128) + blockIdx.x;
    size_t tb = ((size_t)(b * (TT * (FF / 128)) + tile)) * 16384;

    const float* kb = kmat + (size_t)b * CC * S_LAT + t * KK;
    #pragma unroll
    for (int it = 0; it < 8; it++) {
        int idx = tid + it * 256;
        int c = idx >> 4, kq = idx & 15;
        float4 v = *(const float4*)(kb + (size_t)c * S_LAT + kq * 4);
        *(float4*)&Ks[c * 72 + kq * 4] = v;
    }
    const float* qb = q + (size_t)b * CC * S_SIDE + t * FF + fb;
    #pragma unroll
    for (int it = 0; it < 16; it++) {
        int idx = tid + it * 256;
        int c = idx >> 5, fq = idx & 31;
        float4 v = *(const float4*)(qb + (size_t)c * S_SIDE + fq * 4);
        *(float4*)&Qs[c * 128 + fq * 4] = v;
    }
    __syncthreads();

    // phase 1: scores [128f][64k]
    u64 sc2[8][2];
    #pragma unroll
    for (int i = 0; i < 8; i++) { sc2[i][0] = 0ull; sc2[i][1] = 0ull; }

    #pragma unroll 4
    for (int c = 0; c < CC; c++) {
        u64 kp0 = *(const u64*)&Ks[c * 72 + tx * 4];
        u64 kp1 = *(const u64*)&Ks[c * 72 + tx * 4 + 2];
        float4 q0 = *(const float4*)&Qs[c * 128 + ty * 8];
        float4 q1 = *(const float4*)&Qs[c * 128 + ty * 8 + 4];
        u64 qd[8] = {dup2(q0.x),dup2(q0.y),dup2(q0.z),dup2(q0.w),
                     dup2(q1.x),dup2(q1.y),dup2(q1.z),dup2(q1.w)};
        #pragma unroll
        for (int i = 0; i < 8; i++) {
            fma2(sc2[i][0], qd[i], kp0);
            fma2(sc2[i][1], qd[i], kp1);
        }
    }
    float sc[8][4];
    #pragma unroll
    for (int i = 0; i < 8; i++) {
        float2 p0 = unpack2(sc2[i][0]);
        float2 p1 = unpack2(sc2[i][1]);
        sc[i][0] = p0.x; sc[i][1] = p0.y; sc[i][2] = p1.x; sc[i][3] = p1.y;
    }
    float ssv = *ss_p, psv = *ps_p;
    #pragma unroll
    for (int i = 0; i < 8; i++)
        #pragma unroll
        for (int j = 0; j < 4; j++)
            sc[i][j] = sc[i][j] * ssv
                     + basis[(tx * 4 + j) * FF + fb + ty * 8 + i] * psv;
    __syncthreads();

    // softmax over k
    float w[8][4];
    #pragma unroll
    for (int i = 0; i < 8; i++) {
        float m = fmaxf(fmaxf(sc[i][0], sc[i][1]), fmaxf(sc[i][2], sc[i][3]));
        #pragma unroll
        for (int off = 8; off >= 1; off >>= 1)
            m = fmaxf(m, __shfl_xor_sync(0xffffffffu, m, off));
        float e0 = __expf(sc[i][0] - m);
        float e1 = __expf(sc[i][1] - m);
        float e2 = __expf(sc[i][2] - m);
        float e3 = __expf(sc[i][3] - m);
        float s = e0 + e1 + e2 + e3;
        #pragma unroll
        for (int off = 8; off >= 1; off >>= 1)
            s += __shfl_xor_sync(0xffffffffu, s, off);
        float inv = 1.0f / s;
        w[i][0] = e0 * inv; w[i][1] = e1 * inv;
        w[i][2] = e2 * inv; w[i][3] = e3 * inv;
    }
    #pragma unroll
    for (int i = 0; i < 8; i++)
        #pragma unroll
        for (int j = 0; j < 4; j++)
            Wsm[(tx * 4 + j) * 136 + ty * 8 + i] = w[i][j];

    const float* vb = vmat + (size_t)b * CC * S_LAT + t * KK;
    #pragma unroll
    for (int it = 0; it < 8; it++) {
        int idx = tid + it * 256;
        int c = idx >> 4, kq = idx & 15;
        float4 v = *(const float4*)(vb + (size_t)c * S_LAT + kq * 4);
        Vt[(kq * 4 + 0) * 136 + c] = v.x;
        Vt[(kq * 4 + 1) * 136 + c] = v.y;
        Vt[(kq * 4 + 2) * 136 + c] = v.z;
        Vt[(kq * 4 + 3) * 136 + c] = v.w;
    }
    __syncthreads();

    // phase 2: att tile [128c][128f]
    u64 ac2[4][8];
    #pragma unroll
    for (int i = 0; i < 4; i++)
        #pragma unroll
        for (int j = 0; j < 8; j++) ac2[i][j] = 0ull;

    #pragma unroll 4
    for (int k = 0; k < KK; k++) {
        u64 vp[4];
        #pragma unroll
        for (int i = 0; i < 4; i++)
            vp[i] = *(const u64*)&Vt[k * 136 + ty * 8 + 2 * i];
        float4 w0 = *(const float4*)&Wsm[k * 136 + tx * 8];
        float4 w1 = *(const float4*)&Wsm[k * 136 + tx * 8 + 4];
        u64 wd[8] = {dup2(w0.x),dup2(w0.y),dup2(w0.z),dup2(w0.w),
                     dup2(w1.x),dup2(w1.y),dup2(w1.z),dup2(w1.w)};
        #pragma unroll
        for (int i = 0; i < 4; i++)
            #pragma unroll
            for (int j = 0; j < 8; j++)
                fma2(ac2[i][j], vp[i], wd[j]);
    }

    // convert att tile to fp16 [f][c] over the dead Ks region (XOR-swizzled chunks)
    #pragma unroll
    for (int i = 0; i < 4; i++) {
        int c0 = ty * 8 + 2 * i;
        #pragma unroll
        for (int j = 0; j < 8; j++) {
            int f = tx * 8 + j;
            float2 p = unpack2(ac2[i][j]);
            __half h0 = __float2half_rn(p.x);
            __half h1 = __float2half_rn(p.y);
            u32 pk = (u32)*(u16*)&h0 | ((u32)*(u16*)&h1 << 16);
            u32 chunk = (u32)(c0 >> 3) ^ ((u32)(f >> 3) & 7);
            *(u32*)(smb + f * 272 + chunk * 16 + (c0 & 7) * 2) = pk;
        }
    }
    __syncthreads();
    // coalesced copy to global tile (unswizzle)
    {
        u16* thi = tout + tb;
        #pragma unroll
        for (int it = 0; it < 8; it++) {
            int idx = tid + it * 256;
            int f = idx >> 4, lc = idx & 15;
            u32 ch = (u32)lc ^ ((u32)(f >> 3) & 7);
            uint4 wv = *(const uint4*)(smb + f * 272 + ch * 16);
            *(uint4*)(thi + f * 128 + lc * 8) = wv;
        }
    }
}

// ---------------- host ----------------
extern "C" void kernel_launch(void* const* d_in, const int* in_sizes, int n_in,
                              void* d_out, int out_size)
{
    const float* latent     = (const float*)d_in[0];
    const float* side       = (const float*)d_in[1];
    const float* basis      = (const float*)d_in[2];
    const float* lp_gamma   = (const float*)d_in[3];
    const float* lp_w       = (const float*)d_in[4];
    const float* lp_b       = (const float*)d_in[5];
    const float* qn_gamma   = (const float*)d_in[6];
    const float* qmlp_in_w  = (const float*)d_in[7];
    const float* qmlp_in_b  = (const float*)d_in[8];
    const float* qmlp_out_w = (const float*)d_in[9];
    const float* qmlp_out_b = (const float*)d_in[10];
    const float* q_w        = (const float*)d_in[11];
    const float* q_b        = (const float*)d_in[12];
    const float* k_w        = (const float*)d_in[13];
    const float* k_b        = (const float*)d_in[14];
    const float* v_w        = (const float*)d_in[15];
    const float* v_b        = (const float*)d_in[16];
    const float* o_w        = (const float*)d_in[17];
    const float* o_b        = (const float*)d_in[18];
    const float* ffn_gamma  = (const float*)d_in[19];
    const float* ffn_in_w   = (const float*)d_in[20];
    const float* ffn_in_b   = (const float*)d_in[21];
    const float* ffn_out_w  = (const float*)d_in[22];
    const float* ffn_out_b  = (const float*)d_in[23];
    const float* score_sc   = (const float*)d_in[24];
    const float* prior_sc   = (const float*)d_in[25];
    const float* qskip_sc   = (const float*)d_in[26];
    float* out = (float*)d_out;

    float *buf2, *buf3, *kmat, *vmat, *qbias;
    u16 *tA, *tL, *wbf;
    cudaGetSymbolAddress((void**)&buf2, g_buf2);
    cudaGetSymbolAddress((void**)&buf3, g_buf3);
    cudaGetSymbolAddress((void**)&kmat, g_k);
    cudaGetSymbolAddress((void**)&vmat, g_v);
    cudaGetSymbolAddress((void**)&qbias, g_qbias);
    cudaGetSymbolAddress((void**)&tA,   g_tA);
    cudaGetSymbolAddress((void**)&tL,   g_tL);
    cudaGetSymbolAddress((void**)&wbf,  g_wbf);

    cudaFuncSetAttribute(attn_kernel, cudaFuncAttributeMaxDynamicSharedMemorySize, ATT_SMEM_BYTES);
    cudaFuncSetAttribute(gemm_f16in<1,1,1>, cudaFuncAttributeMaxDynamicSharedMemorySize, T16_SMEM);
    cudaFuncSetAttribute(gemm_dual, cudaFuncAttributeMaxDynamicSharedMemorySize, D2_SMEM);
    cudaFuncSetAttribute(gemm_t16<1>, cudaFuncAttributeMaxDynamicSharedMemorySize, T16_SMEM);
    cudaFuncSetAttribute(gemm_t16<2>, cudaFuncAttributeMaxDynamicSharedMemorySize, T16_SMEM);
    cudaFuncSetAttribute(glu_f16, cudaFuncAttributeMaxDynamicSharedMemorySize, GL_SMEM);

    dim3 blk(256);

    // 0: fused weight pre-convert + q-fold
    convert_all<<<704, blk>>>(lp_w, k_w, v_w, qmlp_out_w, o_w, ffn_out_w,
                              qmlp_in_w, ffn_in_w, lp_gamma, qn_gamma, ffn_gamma,
                              q_w, qmlp_out_b, q_b, wbf, qbias);

    // 1: glu1 (fused rms)
    glu_f16<<<dim3(S_SIDE/128, BB), blk, GL_SMEM>>>(side, wbf + WQI, qmlp_in_b, tA, S_SIDE);

    // 2: latent_pre (fused rms, tile out)
    gemm_f16in<1,1,1><<<dim3(S_LAT/128, BB), blk, T16_SMEM>>>(
        latent, wbf + WLP, lp_b, nullptr, tL, S_LAT);

    // 3: merged qmlp_out + q
    gemm_dual<<<dim3(S_SIDE/128, BB), blk, D2_SMEM>>>(
        wbf + WQO, wbf + WQF, qmlp_out_b, qbias, tA, buf3, buf2, S_SIDE);

    // 4: merged k + v
    gemm_dual<<<dim3(S_LAT/128, BB), blk, D2_SMEM>>>(
        wbf + WK, wbf + WV, k_b, v_b, tL, kmat, vmat, S_LAT);

    // 5: attention (fp16 tile out into tA) — PROFILED SLOT
    attn_kernel<<<dim3(FF/128, TT, BB), blk, ATT_SMEM_BYTES>>>(
        buf2, kmat, vmat, basis, score_sc, prior_sc, tA);

    // 6: o-proj (tile in) + query skip
    gemm_t16<1><<<dim3(S_SIDE/128, BB), blk, T16_SMEM>>>(
        wbf + WO, o_b, tA, out, buf3, qskip_sc, S_SIDE);

    // 7: glu2 (fused rms on `out`)
    glu_f16<<<dim3(S_SIDE/128, BB), blk, GL_SMEM>>>(out, wbf + WFI, ffn_in_b, tA, S_SIDE);

    // 8: ffn_out (residual into out)
    gemm_t16<2><<<dim3(S_SIDE/128, BB), blk, T16_SMEM>>>(
        wbf + WFO, ffn_out_b, tA, out, nullptr, nullptr, S_SIDE);
}